// round 12
// baseline (speedup 1.0000x reference)
#include <cuda_runtime.h>
#include <cstdint>

#define Cc 64
#define CO 64
#define Ss 256
#define LL (Ss * Ss)

#define CHUNK 4                 // channels per pipeline stage
#define NCHUNK 16               // Cc / CHUNK
#define NSTAGE 3                // smem ring slots
#define W16 1152                // 16B cp.async ops for w per stage (4ch*9pl*32seg)
#define W_BYTES 18432           // 1152*16
#define X_OFF 18432             // x staging offset within stage
#define E_OFF 20480             // edge scalar offset within stage
#define STAGE_BYTES 20544       // 18432 + 2048 + 64
#define SG_OFF (NSTAGE * STAGE_BYTES)
#define SMEM_TOTAL (SG_OFF + CHUNK * 128 * 4)   // + sg tile (2 KB)

__device__ __forceinline__ void cp16(uint32_t s, const void* g) {
    asm volatile("cp.async.cg.shared.global [%0], [%1], 16;" :: "r"(s), "l"(g));
}
__device__ __forceinline__ void cp4(uint32_t s, const void* g) {
    asm volatile("cp.async.ca.shared.global [%0], [%1], 4;" :: "r"(s), "l"(g));
}
__device__ __forceinline__ void cp_commit() {
    asm volatile("cp.async.commit_group;" ::: "memory");
}
__device__ __forceinline__ void cp_wait2() {
    asm volatile("cp.async.wait_group 2;" ::: "memory");
}

// ---------------------------------------------------------------------------
// cp.async-pipelined fused Reverb kernel.
//   g[c,l]   = x[c,l] * sum_{i,j valid} w[c*9+i*3+j, (y+1-i)*S + (x+1-j)]
//   out[o,l] = sum_c conv[c,o] * g[c,l]
// Block owns 128 px. 3-stage smem ring of RAW w rows (+x, +border scalars),
// filled by cp.async 2 stages ahead (no register staging -> 3 blocks/SM).
// Per chunk: wait+bar, 128 threads compute g[4ch x 128px] from smem rows
// (neighbors read directly; one gmem border scalar per (i,ch) pre-staged),
// bar, 8 warps run the register-tiled mix (conv via __ldg/L1).
// ---------------------------------------------------------------------------
__global__ __launch_bounds__(256, 3) void reverb_cp_kernel(
    const float* __restrict__ x,      // (C, L)
    const float* __restrict__ w,      // (C*9, L)
    const float* __restrict__ conv,   // (C, CO)
    float* __restrict__ out)          // (CO, L)
{
    extern __shared__ __align__(16) unsigned char smem[];
    float* sg = (float*)(smem + SG_OFF);
    const uint32_t smem_u32 = (uint32_t)__cvta_generic_to_shared(smem);

    const int tid = threadIdx.x;
    const int wid = tid >> 5;
    const int lane = tid & 31;

    const int lbase = blockIdx.x * 128;
    const int yb = lbase >> 8;
    const int xb = lbase & 255;

    // y-clamped row offsets + masks (channel-independent)
    float my[3];
    int rowY[3];
#pragma unroll
    for (int i = 0; i < 3; i++) {
        const int ry = yb + 1 - i;
        const bool vy = (unsigned)ry < (unsigned)Ss;
        my[i] = vy ? 1.0f : 0.0f;
        rowY[i] = (vy ? ry : yb) * Ss;
    }

    // ---- per-thread cp.async op descriptors (stage-invariant) ----
    int goff[5];
    uint32_t smoff[5];
#pragma unroll
    for (int k = 0; k < 5; k++) {
        const int id = tid + 256 * k;
        const int idc = (id < W16) ? id : 0;      // dummy for invalid slots
        const int ch = idc / 288;                 // 9*32 ops per channel
        const int rem = idc % 288;
        const int plane = rem >> 5;
        const int seg = rem & 31;
        const int i = plane / 3;
        goff[k] = (ch * 9 + plane) * LL + rowY[i] + xb + seg * 4;
        smoff[k] = (uint32_t)(((ch * 9 + plane) * 32 + seg) * 16);
    }
    // x op (threads 128..255)
    int xgoff = 0;
    uint32_t xsm = 0;
    if (tid >= 128) {
        const int v = tid - 128;
        xgoff = (v >> 5) * LL + lbase + (v & 31) * 4;
        xsm = (uint32_t)(X_OFF + v * 16);
    }
    // border-scalar op (threads 0..11): the one in-row neighbor outside the
    // 128-px tile: x=128 (plane j0) if xb==0, else x=127 (plane j2).
    int egoff = 0;
    if (tid < 12) {
        const int ech = tid / 3;
        const int ei = tid % 3;
        const int jsel = (xb == 0) ? 0 : 2;
        const int exb = (xb == 0) ? 128 : 127;
        egoff = (ech * 9 + ei * 3 + jsel) * LL + rowY[ei] + exb;
    }

    auto issue = [&](int s) {
        const uint32_t sb = smem_u32 + (uint32_t)((s % NSTAGE) * STAGE_BYTES);
        const float* wS = w + (size_t)s * (CHUNK * 9) * LL;
#pragma unroll
        for (int k = 0; k < 5; k++) {
            if (k < 4 || tid < 128) cp16(sb + smoff[k], wS + goff[k]);
        }
        if (tid >= 128) cp16(sb + xsm, x + (size_t)s * CHUNK * LL + xgoff);
        if (tid < 12) cp4(sb + (uint32_t)(E_OFF + tid * 4), wS + egoff);
    };

    unsigned long long acc[4][4];     // [o-pair][pixel]
#pragma unroll
    for (int op = 0; op < 4; op++)
#pragma unroll
        for (int p = 0; p < 4; p++) acc[op][p] = 0ull;

    // ---- prologue: fill 2 stages ----
    issue(0); cp_commit();
    issue(1); cp_commit();

    const int og = wid;

    for (int s = 0; s < NCHUNK; s++) {
        if (s + 2 < NCHUNK) issue(s + 2);
        cp_commit();                   // always commit so group count == stage
        cp_wait2();                    // stage s complete (<=2 pending)
        __syncthreads();               // raw[s%3] visible to all

        // ---- g-compute: threads 0..127, one (channel, 4px) task each ----
        if (tid < 128) {
            const unsigned char* sbc = smem + (s % NSTAGE) * STAGE_BYTES;
            const int cl = tid >> 5;
            const int grp = tid & 31;
            const int x0l = grp * 4;

            const float* base = (const float*)sbc + (cl * 9) * 128;
            const float* eptr = (const float*)(sbc + E_OFF);

            float ws0 = 0.f, ws1 = 0.f, ws2 = 0.f, ws3 = 0.f;
#pragma unroll
            for (int i = 0; i < 3; i++) {
                const float* r0 = base + (3 * i) * 128;      // plane j0 row
                const float* r1 = r0 + 128;                  // j1
                const float* r2 = r0 + 256;                  // j2
                const float4 a = *(const float4*)(r0 + x0l);
                const float4 b = *(const float4*)(r1 + x0l);
                const float4 d = *(const float4*)(r2 + x0l);
                const float ev = eptr[cl * 3 + i];
                const float rsv = (grp < 31) ? r0[x0l + 4]
                                             : ((xb == 128) ? 0.f : ev);
                const float lsv = (grp > 0) ? r2[x0l - 1]
                                            : ((xb == 0) ? 0.f : ev);
                ws0 = fmaf(my[i], (a.y + b.x) + lsv, ws0);
                ws1 = fmaf(my[i], (a.z + b.y) + d.x, ws1);
                ws2 = fmaf(my[i], (a.w + b.z) + d.y, ws2);
                ws3 = fmaf(my[i], (rsv + b.w) + d.z, ws3);
            }
            const float4 xv = *(const float4*)((const float*)(sbc + X_OFF) + cl * 128 + x0l);
            float4 gv;
            gv.x = xv.x * ws0;
            gv.y = xv.y * ws1;
            gv.z = xv.z * ws2;
            gv.w = xv.w * ws3;
            *(float4*)(sg + cl * 128 + x0l) = gv;
        }
        __syncthreads();               // sg ready

        // ---- mix: all 8 warps, 4 channels of this chunk ----
#pragma unroll
        for (int c2 = 0; c2 < CHUNK; c2++) {
            const int c = s * CHUNK + c2;
            const float4 g4 = *(const float4*)(sg + c2 * 128 + lane * 4);
            unsigned long long gp[4];
            asm("mov.b64 %0, {%1, %1};" : "=l"(gp[0]) : "f"(g4.x));
            asm("mov.b64 %0, {%1, %1};" : "=l"(gp[1]) : "f"(g4.y));
            asm("mov.b64 %0, {%1, %1};" : "=l"(gp[2]) : "f"(g4.z));
            asm("mov.b64 %0, {%1, %1};" : "=l"(gp[3]) : "f"(g4.w));

            const ulonglong2 cv = __ldg((const ulonglong2*)(conv + c * CO + og * 8));
            const unsigned long long c01 = cv.x;
            const unsigned long long c23 = cv.y;
            const ulonglong2 cw = __ldg((const ulonglong2*)(conv + c * CO + og * 8 + 4));
            const unsigned long long c45 = cw.x;
            const unsigned long long c67 = cw.y;
#pragma unroll
            for (int p = 0; p < 4; p++) {
                asm("fma.rn.f32x2 %0, %1, %2, %0;" : "+l"(acc[0][p]) : "l"(c01), "l"(gp[p]));
                asm("fma.rn.f32x2 %0, %1, %2, %0;" : "+l"(acc[1][p]) : "l"(c23), "l"(gp[p]));
                asm("fma.rn.f32x2 %0, %1, %2, %0;" : "+l"(acc[2][p]) : "l"(c45), "l"(gp[p]));
                asm("fma.rn.f32x2 %0, %1, %2, %0;" : "+l"(acc[3][p]) : "l"(c67), "l"(gp[p]));
            }
        }
        // next iteration's issue targets slot (s+2)%3, whose readers all
        // finished before the post-g-compute barrier of iteration s-1.
    }

    // ---- Epilogue: unpack, 8 coalesced STG.128 per warp ----
#pragma unroll
    for (int op = 0; op < 4; op++) {
        unsigned int lo[4], hi[4];
#pragma unroll
        for (int p = 0; p < 4; p++) {
            asm("mov.b64 {%0, %1}, %2;" : "=r"(lo[p]), "=r"(hi[p]) : "l"(acc[op][p]));
        }
        const int o = og * 8 + 2 * op;
        float4 v0, v1;
        v0.x = __uint_as_float(lo[0]); v0.y = __uint_as_float(lo[1]);
        v0.z = __uint_as_float(lo[2]); v0.w = __uint_as_float(lo[3]);
        v1.x = __uint_as_float(hi[0]); v1.y = __uint_as_float(hi[1]);
        v1.z = __uint_as_float(hi[2]); v1.w = __uint_as_float(hi[3]);
        *(float4*)(out + (size_t)o * LL + lbase + lane * 4) = v0;
        *(float4*)(out + (size_t)(o + 1) * LL + lbase + lane * 4) = v1;
    }
}

extern "C" void kernel_launch(void* const* d_in, const int* in_sizes, int n_in,
                              void* d_out, int out_size) {
    const float* x    = (const float*)d_in[0];  // (1, C, S, S)
    const float* w    = (const float*)d_in[1];  // (1, C*9, L)
    const float* conv = (const float*)d_in[2];  // (C, CO)
    float* out = (float*)d_out;                 // (1, CO, S, S)

    cudaFuncSetAttribute(reverb_cp_kernel,
                         cudaFuncAttributeMaxDynamicSharedMemorySize, SMEM_TOTAL);
    reverb_cp_kernel<<<LL / 128, 256, SMEM_TOTAL>>>(x, w, conv, out);
}

// round 13
// speedup vs baseline: 1.3314x; 1.3314x over previous
#include <cuda_runtime.h>
#include <cstdint>

#define Cc 64
#define CO 64
#define Ss 256
#define LL (Ss * Ss)

#define CHUNK 4               // channels per pipeline chunk
#define NCHUNK (Cc / CHUNK)   // 16 chunks

// ---------------------------------------------------------------------------
// Software-pipelined fused Reverb kernel (uniform warps, small granule).
//   g[c,l]   = x[c,l] * sum_{i,j valid} w[c*9+i*3+j, (y+1-i)*S + (x+1-j)]
//   out[o,l] = sum_c conv[c,o] * g[c,l]
// Block owns 128 px. Chunk = 4 channels; task = (channel, 2 px) so the
// per-thread prefetch staging is float2 (26 regs), letting 3 blocks/SM fit.
// Loads for chunk s+1 are front-issued before the barrier. Boundary taps
// via warp shuffles; lanes 0/31 carry predicated scalar loads.
// ---------------------------------------------------------------------------
__global__ __launch_bounds__(256, 3) void reverb_pipe_kernel(
    const float* __restrict__ x,      // (C, L)
    const float* __restrict__ w,      // (C*9, L)
    const float* __restrict__ conv,   // (C, CO)
    float* __restrict__ out)          // (CO, L)
{
    __shared__ __align__(16) float sconv[Cc * CO];        // 16 KB
    __shared__ __align__(16) float sg[2][CHUNK * 128];    // 4 KB

    const int tid = threadIdx.x;
    const int wid = tid >> 5;
    const int lane = tid & 31;

    // conv table (first consumer use is after the first __syncthreads)
#pragma unroll
    for (int k = 0; k < 4; k++) {
        const int i = tid + 256 * k;
        ((float4*)sconv)[i] = ((const float4*)conv)[i];
    }

    const int lbase = blockIdx.x * 128;
    const int yb = lbase >> 8;
    const int xb = lbase & 255;

    // Task geometry: channel slot + 2-px group
    const int cl = tid >> 6;          // 0..3
    const int grp = tid & 63;         // 0..63
    const int x0 = xb + grp * 2;

    // Warp-boundary lanes need real scalar loads (shuffle can't cross warps);
    // they coincide with lane 0 / lane 31.
    const bool edgeL = (lane == 0) && (x0 != 0);
    const bool edgeR = (lane == 31) && (x0 != Ss - 2);

    float my[3];
    int rowoff[3];
#pragma unroll
    for (int i = 0; i < 3; i++) {
        const int ry = yb + 1 - i;
        const bool vy = (unsigned)ry < (unsigned)Ss;
        my[i] = vy ? 1.0f : 0.0f;
        rowoff[i] = (vy ? ry : yb) * Ss + x0;
    }

    // Front-batched staging (float2): 9 planes + x + 6 edge scalars
    float2 a[3], b[3], d[3], xv;
    float le[3], re[3];

    auto LOAD = [&](int s) {
        const int c = s * CHUNK + cl;
        const float* wc = w + (size_t)c * 9 * LL;
#pragma unroll
        for (int i = 0; i < 3; i++) {
            const float* p0 = wc + (size_t)(i * 3 + 0) * LL + rowoff[i];
            const float* p1 = wc + (size_t)(i * 3 + 1) * LL + rowoff[i];
            const float* p2 = wc + (size_t)(i * 3 + 2) * LL + rowoff[i];
            a[i] = __ldg((const float2*)p0);
            b[i] = __ldg((const float2*)p1);
            d[i] = __ldg((const float2*)p2);
            le[i] = edgeL ? __ldg(p2 - 1) : 0.0f;
            re[i] = edgeR ? __ldg(p0 + 2) : 0.0f;
        }
        xv = __ldg((const float2*)(x + (size_t)c * LL + lbase + grp * 2));
    };

    unsigned long long acc[4][4];     // [o-pair][pixel]
#pragma unroll
    for (int op = 0; op < 4; op++)
#pragma unroll
        for (int p = 0; p < 4; p++) acc[op][p] = 0ull;

    LOAD(0);

    const int og = wid;               // warp owns outputs [8og, 8og+8)

    for (int s = 0; s < NCHUNK; s++) {
        // ---- g for my (channel, 2px) task ----
        float ws0 = 0.f, ws1 = 0.f;
#pragma unroll
        for (int i = 0; i < 3; i++) {
            // left tap for px0 (plane j2 @ x0-1): prev lane's d.y
            float lsv = __shfl_up_sync(0xffffffffu, d[i].y, 1);
            if (lane == 0) lsv = le[i];
            // right tap for px1 (plane j0 @ x0+2): next lane's a.x
            float rsv = __shfl_down_sync(0xffffffffu, a[i].x, 1);
            if (lane == 31) rsv = re[i];

            ws0 = fmaf(my[i], (a[i].y + b[i].x) + lsv, ws0);
            ws1 = fmaf(my[i], (rsv + b[i].y) + d[i].x, ws1);
        }
        float2 gv;
        gv.x = xv.x * ws0;
        gv.y = xv.y * ws1;
        *(float2*)(&sg[s & 1][cl * 128 + grp * 2]) = gv;

        if (s + 1 < NCHUNK) LOAD(s + 1);   // front-issue before barrier

        __syncthreads();   // chunk s staged (also orders sconv on s==0)

        // ---- mix chunk s from smem (round-8 inner loop, 4 channels) ----
        const float* src = sg[s & 1];
#pragma unroll
        for (int c2 = 0; c2 < CHUNK; c2++) {
            const int c = s * CHUNK + c2;
            const float4 g4 = *(const float4*)(src + c2 * 128 + lane * 4);
            unsigned long long gp[4];
            asm("mov.b64 %0, {%1, %1};" : "=l"(gp[0]) : "f"(g4.x));
            asm("mov.b64 %0, {%1, %1};" : "=l"(gp[1]) : "f"(g4.y));
            asm("mov.b64 %0, {%1, %1};" : "=l"(gp[2]) : "f"(g4.z));
            asm("mov.b64 %0, {%1, %1};" : "=l"(gp[3]) : "f"(g4.w));

            const ulonglong2* cv = (const ulonglong2*)(sconv + c * CO + og * 8);
            const ulonglong2 cva = cv[0];
            const ulonglong2 cvb = cv[1];
#pragma unroll
            for (int p = 0; p < 4; p++) {
                asm("fma.rn.f32x2 %0, %1, %2, %0;" : "+l"(acc[0][p]) : "l"(cva.x), "l"(gp[p]));
                asm("fma.rn.f32x2 %0, %1, %2, %0;" : "+l"(acc[1][p]) : "l"(cva.y), "l"(gp[p]));
                asm("fma.rn.f32x2 %0, %1, %2, %0;" : "+l"(acc[2][p]) : "l"(cvb.x), "l"(gp[p]));
                asm("fma.rn.f32x2 %0, %1, %2, %0;" : "+l"(acc[3][p]) : "l"(cvb.y), "l"(gp[p]));
            }
        }
        // Double buffering + one barrier per chunk protect the ring:
        // STS(s+1) targets the other buffer; readers of that buffer (mix of
        // chunk s-1) all passed this iteration's barrier already.
    }

    // ---- Epilogue: unpack, 8 coalesced STG.128 per warp ----
#pragma unroll
    for (int op = 0; op < 4; op++) {
        unsigned int lo[4], hi[4];
#pragma unroll
        for (int p = 0; p < 4; p++) {
            asm("mov.b64 {%0, %1}, %2;" : "=r"(lo[p]), "=r"(hi[p]) : "l"(acc[op][p]));
        }
        const int o = og * 8 + 2 * op;
        float4 v0, v1;
        v0.x = __uint_as_float(lo[0]); v0.y = __uint_as_float(lo[1]);
        v0.z = __uint_as_float(lo[2]); v0.w = __uint_as_float(lo[3]);
        v1.x = __uint_as_float(hi[0]); v1.y = __uint_as_float(hi[1]);
        v1.z = __uint_as_float(hi[2]); v1.w = __uint_as_float(hi[3]);
        *(float4*)(out + (size_t)o * LL + lbase + lane * 4) = v0;
        *(float4*)(out + (size_t)(o + 1) * LL + lbase + lane * 4) = v1;
    }
}

extern "C" void kernel_launch(void* const* d_in, const int* in_sizes, int n_in,
                              void* d_out, int out_size) {
    const float* x    = (const float*)d_in[0];  // (1, C, S, S)
    const float* w    = (const float*)d_in[1];  // (1, C*9, L)
    const float* conv = (const float*)d_in[2];  // (C, CO)
    float* out = (float*)d_out;                 // (1, CO, S, S)

    reverb_pipe_kernel<<<LL / 128, 256>>>(x, w, conv, out);
}

// round 14
// speedup vs baseline: 1.6377x; 1.2301x over previous
#include <cuda_runtime.h>
#include <cstdint>

#define Cc 64
#define CO 64
#define Ss 256
#define LL (Ss * Ss)

#define CHUNK 8               // channels per pipeline chunk
#define NCHUNK (Cc / CHUNK)   // 8 chunks

// ---------------------------------------------------------------------------
// Software-pipelined fused Reverb kernel (round-11 structure + L2 prefetch).
//   g[c,l]   = x[c,l] * sum_{i,j valid} w[c*9+i*3+j, (y+1-i)*S + (x+1-j)]
//   out[o,l] = sum_c conv[c,o] * g[c,l]
// Block owns 128 px. Task = (channel, 4px); 10 front-issued float4 LDGs per
// chunk; chunk s+1 loads issued before the barrier; chunk s+2 lines pulled
// into L2 via prefetch.global.L2 (zero register staging) so the real LDGs
// hit L2 instead of DRAM. Boundary taps via warp shuffles.
// ---------------------------------------------------------------------------
__global__ __launch_bounds__(256, 2) void reverb_pipe_kernel(
    const float* __restrict__ x,      // (C, L)
    const float* __restrict__ w,      // (C*9, L)
    const float* __restrict__ conv,   // (C, CO)
    float* __restrict__ out)          // (CO, L)
{
    __shared__ __align__(16) float sconv[Cc * CO];        // 16 KB
    __shared__ __align__(16) float sg[2][CHUNK * 128];    // 8 KB

    const int tid = threadIdx.x;
    const int wid = tid >> 5;
    const int lane = tid & 31;

#pragma unroll
    for (int k = 0; k < 4; k++) {
        const int i = tid + 256 * k;
        ((float4*)sconv)[i] = ((const float4*)conv)[i];
    }

    const int lbase = blockIdx.x * 128;
    const int yb = lbase >> 8;
    const int xb = lbase & 255;

    const int cl = wid;               // channel slot within chunk
    const int grp = lane;             // 4-px group
    const int x0 = xb + grp * 4;

    const bool edgeL = (lane == 0) && (x0 != 0);
    const bool edgeR = (lane == 31) && (x0 != Ss - 4);

    float my[3];
    int rowoff[3];
#pragma unroll
    for (int i = 0; i < 3; i++) {
        const int ry = yb + 1 - i;
        const bool vy = (unsigned)ry < (unsigned)Ss;
        my[i] = vy ? 1.0f : 0.0f;
        rowoff[i] = (vy ? ry : yb) * Ss + x0;
    }

    float4 a[3], b[3], d[3], xv;
    float le[3], re[3];

    auto LOAD = [&](int s) {
        const int c = s * CHUNK + cl;
        const float* wc = w + (size_t)c * 9 * LL;
#pragma unroll
        for (int i = 0; i < 3; i++) {
            const float* p0 = wc + (size_t)(i * 3 + 0) * LL + rowoff[i];
            const float* p1 = wc + (size_t)(i * 3 + 1) * LL + rowoff[i];
            const float* p2 = wc + (size_t)(i * 3 + 2) * LL + rowoff[i];
            a[i] = __ldg((const float4*)p0);
            b[i] = __ldg((const float4*)p1);
            d[i] = __ldg((const float4*)p2);
            le[i] = edgeL ? __ldg(p2 - 1) : 0.0f;
            re[i] = edgeR ? __ldg(p0 + 4) : 0.0f;
        }
        xv = __ldg((const float4*)(x + (size_t)c * LL + lbase + grp * 4));
    };

    // Pull chunk s's lines into L2 (no register staging, no dependency)
    auto PREF = [&](int s) {
        const int c = s * CHUNK + cl;
        const float* wc = w + (size_t)c * 9 * LL;
#pragma unroll
        for (int i = 0; i < 3; i++) {
#pragma unroll
            for (int j = 0; j < 3; j++) {
                const float* p = wc + (size_t)(i * 3 + j) * LL + rowoff[i];
                asm volatile("prefetch.global.L2 [%0];" :: "l"(p));
            }
        }
        asm volatile("prefetch.global.L2 [%0];"
                     :: "l"(x + (size_t)c * LL + lbase + grp * 4));
    };

    unsigned long long acc[4][4];     // [o-pair][pixel]
#pragma unroll
    for (int op = 0; op < 4; op++)
#pragma unroll
        for (int p = 0; p < 4; p++) acc[op][p] = 0ull;

    LOAD(0);
    PREF(1);

    const int og = wid;

    for (int s = 0; s < NCHUNK; s++) {
        // ---- g for my (channel, 4px) task ----
        float ws0 = 0.f, ws1 = 0.f, ws2 = 0.f, ws3 = 0.f;
#pragma unroll
        for (int i = 0; i < 3; i++) {
            float lsv = __shfl_up_sync(0xffffffffu, d[i].w, 1);
            if (lane == 0) lsv = le[i];
            float rsv = __shfl_down_sync(0xffffffffu, a[i].x, 1);
            if (lane == 31) rsv = re[i];

            ws0 = fmaf(my[i], (a[i].y + b[i].x) + lsv, ws0);
            ws1 = fmaf(my[i], (a[i].z + b[i].y) + d[i].x, ws1);
            ws2 = fmaf(my[i], (a[i].w + b[i].z) + d[i].y, ws2);
            ws3 = fmaf(my[i], (rsv + b[i].w) + d[i].z, ws3);
        }
        float4 gv;
        gv.x = xv.x * ws0;
        gv.y = xv.y * ws1;
        gv.z = xv.z * ws2;
        gv.w = xv.w * ws3;
        *(float4*)(&sg[s & 1][cl * 128 + grp * 4]) = gv;

        // Real loads for s+1 (mostly L2 hits thanks to PREF), then L2
        // prefetch for s+2 — both before the barrier.
        if (s + 1 < NCHUNK) LOAD(s + 1);
        if (s + 2 < NCHUNK) PREF(s + 2);

        __syncthreads();   // chunk s staged (also orders sconv on s==0)

        // ---- mix chunk s from smem ----
        const float* src = sg[s & 1];
#pragma unroll
        for (int c2 = 0; c2 < CHUNK; c2++) {
            const int c = s * CHUNK + c2;
            const float4 g4 = *(const float4*)(src + c2 * 128 + lane * 4);
            unsigned long long gp[4];
            asm("mov.b64 %0, {%1, %1};" : "=l"(gp[0]) : "f"(g4.x));
            asm("mov.b64 %0, {%1, %1};" : "=l"(gp[1]) : "f"(g4.y));
            asm("mov.b64 %0, {%1, %1};" : "=l"(gp[2]) : "f"(g4.z));
            asm("mov.b64 %0, {%1, %1};" : "=l"(gp[3]) : "f"(g4.w));

            const ulonglong2* cv = (const ulonglong2*)(sconv + c * CO + og * 8);
            const ulonglong2 cva = cv[0];
            const ulonglong2 cvb = cv[1];
#pragma unroll
            for (int p = 0; p < 4; p++) {
                asm("fma.rn.f32x2 %0, %1, %2, %0;" : "+l"(acc[0][p]) : "l"(cva.x), "l"(gp[p]));
                asm("fma.rn.f32x2 %0, %1, %2, %0;" : "+l"(acc[1][p]) : "l"(cva.y), "l"(gp[p]));
                asm("fma.rn.f32x2 %0, %1, %2, %0;" : "+l"(acc[2][p]) : "l"(cvb.x), "l"(gp[p]));
                asm("fma.rn.f32x2 %0, %1, %2, %0;" : "+l"(acc[3][p]) : "l"(cvb.y), "l"(gp[p]));
            }
        }
    }

    // ---- Epilogue: unpack, 8 coalesced STG.128 per warp ----
#pragma unroll
    for (int op = 0; op < 4; op++) {
        unsigned int lo[4], hi[4];
#pragma unroll
        for (int p = 0; p < 4; p++) {
            asm("mov.b64 {%0, %1}, %2;" : "=r"(lo[p]), "=r"(hi[p]) : "l"(acc[op][p]));
        }
        const int o = og * 8 + 2 * op;
        float4 v0, v1;
        v0.x = __uint_as_float(lo[0]); v0.y = __uint_as_float(lo[1]);
        v0.z = __uint_as_float(lo[2]); v0.w = __uint_as_float(lo[3]);
        v1.x = __uint_as_float(hi[0]); v1.y = __uint_as_float(hi[1]);
        v1.z = __uint_as_float(hi[2]); v1.w = __uint_as_float(hi[3]);
        *(float4*)(out + (size_t)o * LL + lbase + lane * 4) = v0;
        *(float4*)(out + (size_t)(o + 1) * LL + lbase + lane * 4) = v1;
    }
}

extern "C" void kernel_launch(void* const* d_in, const int* in_sizes, int n_in,
                              void* d_out, int out_size) {
    const float* x    = (const float*)d_in[0];  // (1, C, S, S)
    const float* w    = (const float*)d_in[1];  // (1, C*9, L)
    const float* conv = (const float*)d_in[2];  // (C, CO)
    float* out = (float*)d_out;                 // (1, CO, S, S)

    reverb_pipe_kernel<<<LL / 128, 256>>>(x, w, conv, out);
}